// round 6
// baseline (speedup 1.0000x reference)
#include <cuda_runtime.h>

#define IMW 1024
#define IMH 1024
#define HW  (IMW * IMH)
#define TW 16
#define TH 16
#define HALO 22
#define CSTR 22                   // ull per pair-row
#define EPAIRS 11                 // E[k] = rows (2k, 2k+1)
#define OPAIRS 10                 // O[k] = rows (2k+1, 2k+2)
#define ECH (EPAIRS * CSTR)       // 242 ull / channel
#define OCH (OPAIRS * CSTR)       // 220 ull / channel
#define E_ULL (11 * ECH)          // 2662
#define O_ULL (11 * OCH)          // 2420
#define NPAIR 128
#define XSTR 31                   // conflict-free exchange stride
#define X_ULL (NPAIR * XSTR)      // 3968
#define SMEM_BYTES ((E_ULL + O_ULL + X_ULL) * 8)   // 72,400 B
#define EPSR 1e-4f

typedef unsigned long long ull;

// ---- packed f32x2 helpers -------------------------------------------------
__device__ __forceinline__ ull pk2(float lo, float hi) {
    ull r;
    asm("mov.b64 %0, {%1, %2};" : "=l"(r) : "f"(lo), "f"(hi));
    return r;
}
__device__ __forceinline__ void ffma2(ull& d, ull a, ull b) {
    asm("fma.rn.f32x2 %0, %1, %2, %0;" : "+l"(d) : "l"(a), "l"(b));
}
__device__ __forceinline__ ull ffma2g(ull a, ull b, ull c) {
    ull r;
    asm("fma.rn.f32x2 %0, %1, %2, %3;" : "=l"(r) : "l"(a), "l"(b), "l"(c));
    return r;
}
__device__ __forceinline__ ull mul2(ull a, ull b) {
    ull r;
    asm("mul.rn.f32x2 %0, %1, %2;" : "=l"(r) : "l"(a), "l"(b));
    return r;
}
__device__ __forceinline__ ull add2(ull a, ull b) {
    ull r;
    asm("add.rn.f32x2 %0, %1, %2;" : "=l"(r) : "l"(a), "l"(b));
    return r;
}
__device__ __forceinline__ void upk2(ull v, float& lo, float& hi) {
    asm("mov.b64 {%0, %1}, %2;" : "=f"(lo), "=f"(hi) : "l"(v));
}
__device__ __forceinline__ float frcp(float x) {
    float r;
    asm("rcp.approx.f32 %0, %1;" : "=f"(r) : "f"(x));
    return r;
}
__host__ __device__ constexpr int IDX(int i, int j) {  // upper-tri 8x8, i<=j
    return i * 8 - i * (i - 1) / 2 + (j - i);
}

// g0: 30 moments = tri rows 0..4  (needs ch 0..7)
__device__ __forceinline__ void fma30a(const ull v[8], ull acc[30]) {
    int k = 0;
#pragma unroll
    for (int i = 0; i < 5; ++i)
#pragma unroll
        for (int j = i; j < 8; ++j) { ffma2(acc[k], v[i], v[j]); ++k; }
}
// g1: 30 moments = tri{5,6,7} (6) + AtY (24)   (needs ch 0..10)
__device__ __forceinline__ void fma30b(const ull v[11], ull acc[30]) {
    int k = 0;
#pragma unroll
    for (int i = 5; i < 8; ++i)
#pragma unroll
        for (int j = i; j < 8; ++j) { ffma2(acc[k], v[i], v[j]); ++k; }
#pragma unroll
    for (int i = 0; i < 8; ++i)
#pragma unroll
        for (int c = 0; c < 3; ++c) { ffma2(acc[k], v[i], v[8 + c]); ++k; }
}

__global__ __launch_bounds__(256, 2)
void ls_kernel(const float* __restrict__ inp,
               const float* __restrict__ depth,
               const float* __restrict__ alb,
               const float* __restrict__ nrm,
               float* __restrict__ out)
{
    extern __shared__ ull SMU[];
    ull* E = SMU;                     // E[ch][k][col] = (f[2k], f[2k+1])
    ull* O = SMU + E_ULL;             // O[ch][k][col] = (f[2k+1], f[2k+2])
    ull* X = SMU + E_ULL + O_ULL;     // exchange: X[p*31 + m]
    float* Ew = (float*)E;
    float* Ow = (float*)O;

    const int tid = threadIdx.x;
    const int bx = blockIdx.x, by = blockIdx.y;
    const int gx0 = bx * TW - 3;
    const int gy0 = by * TH - 3;

    // ---- stage halo features into both parity-paired layouts ----
    for (int idx = tid; idx < HALO * HALO; idx += 256) {
        const int r = idx / HALO;
        const int c = idx - r * HALO;
        const int gy = gy0 + r;
        const int gx = gx0 + c;
        float v[11];
        if ((unsigned)gy < (unsigned)IMH && (unsigned)gx < (unsigned)IMW) {
            const int g = gy * IMW + gx;
            v[0] = 1.0f;
            v[1] = depth[g];
            v[2] = alb[g];  v[3] = alb[g + HW];  v[4] = alb[g + 2 * HW];
            v[5] = nrm[g];  v[6] = nrm[g + HW];  v[7] = nrm[g + 2 * HW];
            v[8] = inp[g];  v[9] = inp[g + HW];  v[10] = inp[g + 2 * HW];
        } else {
#pragma unroll
            for (int ch = 0; ch < 11; ++ch) v[ch] = 0.0f;
        }
        if (r & 1) {
            const int ke = r >> 1;           // E[ke] hi
#pragma unroll
            for (int ch = 0; ch < 11; ++ch) {
                Ew[(ch * ECH + ke * CSTR + c) * 2 + 1] = v[ch];
                if (r < HALO - 1)
                    Ow[(ch * OCH + ke * CSTR + c) * 2 + 0] = v[ch];
            }
        } else {
            const int ke = r >> 1;           // E[ke] lo
            const int ko = ke - 1;           // O[ko] hi
#pragma unroll
            for (int ch = 0; ch < 11; ++ch) {
                Ew[(ch * ECH + ke * CSTR + c) * 2 + 0] = v[ch];
                if (r >= 2)
                    Ow[(ch * OCH + ko * CSTR + c) * 2 + 1] = v[ch];
            }
        }
    }
    __syncthreads();

    const int grp = tid >> 7;            // 0: AtA tri rows 0..4; 1: rest
    const int p = tid & 127;             // pair id
    const int lx = p & 15;
    const int ty = p >> 4;               // 0..7; output rows 2ty, 2ty+1

    // window row L = 2ty+dy; pair (L,L+1): dy even -> E[ty+dy/2], odd -> O[ty+(dy-1)/2]
    if (grp == 0) {
        ull acc[30];
#pragma unroll
        for (int m = 0; m < 30; ++m) acc[m] = 0ULL;
        const ull* eb = E + ty * CSTR + lx;
        const ull* ob = O + ty * CSTR + lx;
#pragma unroll 1
        for (int j = 0; j < 3; ++j) {
#pragma unroll
            for (int dx = 0; dx < 7; ++dx) {
                ull v[8];
#pragma unroll
                for (int ch = 0; ch < 8; ++ch) v[ch] = eb[ch * ECH + dx];
                fma30a(v, acc);
            }
#pragma unroll
            for (int dx = 0; dx < 7; ++dx) {
                ull v[8];
#pragma unroll
                for (int ch = 0; ch < 8; ++ch) v[ch] = ob[ch * OCH + dx];
                fma30a(v, acc);
            }
            eb += CSTR;
            ob += CSTR;
        }
#pragma unroll
        for (int dx = 0; dx < 7; ++dx) {
            ull v[8];
#pragma unroll
            for (int ch = 0; ch < 8; ++ch) v[ch] = eb[ch * ECH + dx];
            fma30a(v, acc);
        }
        __syncthreads();

        // ---- assemble + packed symmetric solve ----
        ull ata[36];
#pragma unroll
        for (int m = 0; m < 30; ++m) ata[m] = acc[m];
        const ull* xp = X + p * XSTR;
#pragma unroll
        for (int m = 0; m < 6; ++m) ata[30 + m] = xp[m];

        const ull EPS2 = pk2(EPSR, EPSR);
#pragma unroll
        for (int i = 0; i < 8; ++i) ata[IDX(i, i)] = add2(ata[IDX(i, i)], EPS2);

        ull rhs[8];
        {
            const ull* cp = O + (ty + 1) * CSTR + (lx + 3);
#pragma unroll
            for (int ch = 0; ch < 8; ++ch) rhs[ch] = cp[ch * OCH];
        }

#pragma unroll
        for (int k = 0; k < 8; ++k) {
            float dlo, dhi;
            upk2(ata[IDX(k, k)], dlo, dhi);
            const ull ninv = pk2(-frcp(dlo), -frcp(dhi));
#pragma unroll
            for (int i = k + 1; i < 8; ++i) {
                const ull li = mul2(ata[IDX(k, i)], ninv);   // -a_ki / d_k
                rhs[i] = ffma2g(li, rhs[k], rhs[i]);
#pragma unroll
                for (int j = i; j < 8; ++j)
                    ata[IDX(i, j)] = ffma2g(li, ata[IDX(k, j)], ata[IDX(i, j)]);
            }
        }
        ull nx[8];
#pragma unroll
        for (int i = 7; i >= 0; --i) {
            ull s = rhs[i];
#pragma unroll
            for (int j = 7; j > i; --j)
                s = ffma2g(ata[IDX(i, j)], nx[j], s);
            float dlo, dhi;
            upk2(ata[IDX(i, i)], dlo, dhi);
            nx[i] = mul2(s, pk2(-frcp(dlo), -frcp(dhi)));
        }

        // out_c = x . AtY_c = -(nx . AtY_c), AtY from exchange buffer
        const int gy = by * TH + 2 * ty;
        const int gx = bx * TW + lx;
#pragma unroll
        for (int c = 0; c < 3; ++c) {
            ull acc2 = 0ULL;
#pragma unroll
            for (int i = 0; i < 8; ++i)
                ffma2(acc2, nx[i], xp[6 + i * 3 + c]);
            float olo, ohi;
            upk2(acc2, olo, ohi);
            out[c * HW + gy * IMW + gx]       = -olo;
            out[c * HW + (gy + 1) * IMW + gx] = -ohi;
        }
    } else {
        ull acc[30];
#pragma unroll
        for (int m = 0; m < 30; ++m) acc[m] = 0ULL;
        const ull* eb = E + ty * CSTR + lx;
        const ull* ob = O + ty * CSTR + lx;
#pragma unroll 1
        for (int j = 0; j < 3; ++j) {
#pragma unroll
            for (int dx = 0; dx < 7; ++dx) {
                ull v[11];
#pragma unroll
                for (int ch = 0; ch < 11; ++ch) v[ch] = eb[ch * ECH + dx];
                fma30b(v, acc);
            }
#pragma unroll
            for (int dx = 0; dx < 7; ++dx) {
                ull v[11];
#pragma unroll
                for (int ch = 0; ch < 11; ++ch) v[ch] = ob[ch * OCH + dx];
                fma30b(v, acc);
            }
            eb += CSTR;
            ob += CSTR;
        }
#pragma unroll
        for (int dx = 0; dx < 7; ++dx) {
            ull v[11];
#pragma unroll
            for (int ch = 0; ch < 11; ++ch) v[ch] = eb[ch * ECH + dx];
            fma30b(v, acc);
        }
        // hand off 6 tri + 24 AtY
        ull* xp = X + p * XSTR;
#pragma unroll
        for (int m = 0; m < 30; ++m) xp[m] = acc[m];
        __syncthreads();
        // done; g0 finishes the solve
    }
}

extern "C" void kernel_launch(void* const* d_in, const int* in_sizes, int n_in,
                              void* d_out, int out_size) {
    const float* inp   = (const float*)d_in[0];
    const float* depth = (const float*)d_in[1];
    const float* alb   = (const float*)d_in[2];
    const float* nrm   = (const float*)d_in[3];
    float* out = (float*)d_out;

    cudaFuncSetAttribute(ls_kernel, cudaFuncAttributeMaxDynamicSharedMemorySize,
                         SMEM_BYTES);
    dim3 grid(IMW / TW, IMH / TH);
    ls_kernel<<<grid, 256, SMEM_BYTES>>>(inp, depth, alb, nrm, out);
}

// round 7
// speedup vs baseline: 1.0877x; 1.0877x over previous
#include <cuda_runtime.h>

#define IMW 1024
#define IMH 1024
#define HW  (IMW * IMH)
#define TW 16
#define TH 16
#define HALO 22
#define SSTRIDE 24
#define CH_STRIDE (HALO * SSTRIDE)     // 528 floats per channel
#define F_WORDS (11 * CH_STRIDE)       // 5808 floats
#define NPAIR 128
#define XSTR 31                         // exchange stride (ull)
#define X_ULL (NPAIR * XSTR)            // 3968 ull
#define SMEM_BYTES (F_WORDS * 4 + X_ULL * 8)   // 23232 + 31744 = 54976 B
#define EPSR 1e-4f

typedef unsigned long long ull;

// ---- packed f32x2 helpers -------------------------------------------------
__device__ __forceinline__ ull pk2(float lo, float hi) {
    ull r;
    asm("mov.b64 %0, {%1, %2};" : "=l"(r) : "f"(lo), "f"(hi));
    return r;
}
__device__ __forceinline__ void ffma2(ull& d, ull a, ull b) {
    asm("fma.rn.f32x2 %0, %1, %2, %0;" : "+l"(d) : "l"(a), "l"(b));
}
__device__ __forceinline__ ull ffma2g(ull a, ull b, ull c) {
    ull r;
    asm("fma.rn.f32x2 %0, %1, %2, %3;" : "=l"(r) : "l"(a), "l"(b), "l"(c));
    return r;
}
__device__ __forceinline__ ull mul2(ull a, ull b) {
    ull r;
    asm("mul.rn.f32x2 %0, %1, %2;" : "=l"(r) : "l"(a), "l"(b));
    return r;
}
__device__ __forceinline__ ull add2(ull a, ull b) {
    ull r;
    asm("add.rn.f32x2 %0, %1, %2;" : "=l"(r) : "l"(a), "l"(b));
    return r;
}
__device__ __forceinline__ void upk2(ull v, float& lo, float& hi) {
    asm("mov.b64 {%0, %1}, %2;" : "=f"(lo), "=f"(hi) : "l"(v));
}
__device__ __forceinline__ float frcp(float x) {
    float r;
    asm("rcp.approx.f32 %0, %1;" : "=f"(r) : "f"(x));
    return r;
}
__host__ __device__ constexpr int IDX(int i, int j) {  // upper-tri 8x8, i<=j
    return i * 8 - i * (i - 1) / 2 + (j - i);
}

__global__ __launch_bounds__(256, 2)
void ls_kernel(const float* __restrict__ inp,
               const float* __restrict__ depth,
               const float* __restrict__ alb,
               const float* __restrict__ nrm,
               float* __restrict__ out)
{
    extern __shared__ float SM[];
    float* S = SM;                           // S[ch][r][c], stride 24
    ull* X = (ull*)(SM + F_WORDS);           // exchange: X[p*31 + m]

    const int tid = threadIdx.x;
    const int bx = blockIdx.x, by = blockIdx.y;
    const int gx0 = bx * TW - 3;
    const int gy0 = by * TH - 3;

    // ---- stage halo features (zeros outside image) ----
    for (int idx = tid; idx < HALO * HALO; idx += 256) {
        const int r = idx / HALO;
        const int c = idx - r * HALO;
        const int gy = gy0 + r;
        const int gx = gx0 + c;
        float v[11];
        if ((unsigned)gy < (unsigned)IMH && (unsigned)gx < (unsigned)IMW) {
            const int g = gy * IMW + gx;
            v[0] = 1.0f;
            v[1] = depth[g];
            v[2] = alb[g];  v[3] = alb[g + HW];  v[4] = alb[g + 2 * HW];
            v[5] = nrm[g];  v[6] = nrm[g + HW];  v[7] = nrm[g + 2 * HW];
            v[8] = inp[g];  v[9] = inp[g + HW];  v[10] = inp[g + 2 * HW];
        } else {
#pragma unroll
            for (int ch = 0; ch < 11; ++ch) v[ch] = 0.0f;
        }
#pragma unroll
        for (int ch = 0; ch < 11; ++ch)
            S[ch * CH_STRIDE + r * SSTRIDE + c] = v[ch];
    }
    __syncthreads();

    const int grp = tid >> 7;            // 0: AtA tri rows 0..4 + solve; 1: rest
    const int p = tid & 127;             // pair id
    const int lx = p & 15;
    const int ty = p >> 4;               // 0..7; output rows 2ty, 2ty+1

    if (grp == 0) {
        // ---- g0: 30 moments = AtA tri rows 0..4 (ch 0..7) ----
        ull acc[30];
#pragma unroll
        for (int m = 0; m < 30; ++m) acc[m] = 0ULL;
        const float* base = &S[2 * ty * SSTRIDE + lx];
#pragma unroll 1
        for (int dy = 0; dy < 7; ++dy) {
            const float* rp = base + dy * SSTRIDE;
#pragma unroll
            for (int dx = 0; dx < 7; ++dx) {
                ull v[8];
#pragma unroll
                for (int ch = 0; ch < 8; ++ch)
                    v[ch] = pk2(rp[ch * CH_STRIDE + dx],
                                rp[ch * CH_STRIDE + dx + SSTRIDE]);
                int k = 0;
#pragma unroll
                for (int i = 0; i < 5; ++i)
#pragma unroll
                    for (int j = i; j < 8; ++j) { ffma2(acc[k], v[i], v[j]); ++k; }
            }
        }
        __syncthreads();

        // ---- assemble AtA + packed symmetric solve ----
        ull ata[36];
#pragma unroll
        for (int m = 0; m < 30; ++m) ata[m] = acc[m];
        const ull* xp = X + p * XSTR;
#pragma unroll
        for (int m = 0; m < 6; ++m) ata[30 + m] = xp[m];

        const ull EPS2 = pk2(EPSR, EPSR);
#pragma unroll
        for (int i = 0; i < 8; ++i) ata[IDX(i, i)] = add2(ata[IDX(i, i)], EPS2);

        ull rhs[8];
        {
            const float* cp = &S[(2 * ty + 3) * SSTRIDE + (lx + 3)];
#pragma unroll
            for (int ch = 0; ch < 8; ++ch)
                rhs[ch] = pk2(cp[ch * CH_STRIDE], cp[ch * CH_STRIDE + SSTRIDE]);
        }

#pragma unroll
        for (int k = 0; k < 8; ++k) {
            float dlo, dhi;
            upk2(ata[IDX(k, k)], dlo, dhi);
            const ull ninv = pk2(-frcp(dlo), -frcp(dhi));
#pragma unroll
            for (int i = k + 1; i < 8; ++i) {
                const ull li = mul2(ata[IDX(k, i)], ninv);   // -a_ki / d_k
                rhs[i] = ffma2g(li, rhs[k], rhs[i]);
#pragma unroll
                for (int j = i; j < 8; ++j)
                    ata[IDX(i, j)] = ffma2g(li, ata[IDX(k, j)], ata[IDX(i, j)]);
            }
        }
        ull nx[8];
#pragma unroll
        for (int i = 7; i >= 0; --i) {
            ull s = rhs[i];
#pragma unroll
            for (int j = 7; j > i; --j)
                s = ffma2g(ata[IDX(i, j)], nx[j], s);
            float dlo, dhi;
            upk2(ata[IDX(i, i)], dlo, dhi);
            nx[i] = mul2(s, pk2(-frcp(dlo), -frcp(dhi)));
        }

        // out_c = x . AtY_c = -(nx . AtY_c); AtY lives in exchange buffer
        const int gy = by * TH + 2 * ty;
        const int gx = bx * TW + lx;
#pragma unroll
        for (int c = 0; c < 3; ++c) {
            ull a2 = 0ULL;
#pragma unroll
            for (int i = 0; i < 8; ++i)
                ffma2(a2, nx[i], xp[6 + i * 3 + c]);
            float olo, ohi;
            upk2(a2, olo, ohi);
            out[c * HW + gy * IMW + gx]       = -olo;
            out[c * HW + (gy + 1) * IMW + gx] = -ohi;
        }
    } else {
        // ---- g1: 30 moments = tri{5,6,7} (6) + AtY (24), ch 0..10 ----
        ull acc[30];
#pragma unroll
        for (int m = 0; m < 30; ++m) acc[m] = 0ULL;
        const float* base = &S[2 * ty * SSTRIDE + lx];
#pragma unroll 1
        for (int dy = 0; dy < 7; ++dy) {
            const float* rp = base + dy * SSTRIDE;
#pragma unroll
            for (int dx = 0; dx < 7; ++dx) {
                ull v[11];
#pragma unroll
                for (int ch = 0; ch < 11; ++ch)
                    v[ch] = pk2(rp[ch * CH_STRIDE + dx],
                                rp[ch * CH_STRIDE + dx + SSTRIDE]);
                int k = 0;
#pragma unroll
                for (int i = 5; i < 8; ++i)
#pragma unroll
                    for (int j = i; j < 8; ++j) { ffma2(acc[k], v[i], v[j]); ++k; }
#pragma unroll
                for (int i = 0; i < 8; ++i)
#pragma unroll
                    for (int c = 0; c < 3; ++c) { ffma2(acc[k], v[i], v[8 + c]); ++k; }
            }
        }
        // hand off: 6 tri + 24 AtY
        ull* xp = X + p * XSTR;
#pragma unroll
        for (int m = 0; m < 30; ++m) xp[m] = acc[m];
        __syncthreads();
        // g0 finishes the solve
    }
}

extern "C" void kernel_launch(void* const* d_in, const int* in_sizes, int n_in,
                              void* d_out, int out_size) {
    const float* inp   = (const float*)d_in[0];
    const float* depth = (const float*)d_in[1];
    const float* alb   = (const float*)d_in[2];
    const float* nrm   = (const float*)d_in[3];
    float* out = (float*)d_out;

    cudaFuncSetAttribute(ls_kernel, cudaFuncAttributeMaxDynamicSharedMemorySize,
                         SMEM_BYTES);
    dim3 grid(IMW / TW, IMH / TH);
    ls_kernel<<<grid, 256, SMEM_BYTES>>>(inp, depth, alb, nrm, out);
}